// round 1
// baseline (speedup 1.0000x reference)
#include <cuda_runtime.h>
#include <cuda_bf16.h>

// Fused: conv2d 3x3 VALID (NCHW/OIHW) + bias + mish + BN-inference affine.
// N=32, Cin=64, H=W=128, Cout=128, Hout=Wout=126.
//
// Block: 256 threads = 16x16 output pixels, 32 output channels, one image.
// Grid: (8*8 spatial tiles, 4 oc groups, 32 images).

#define TILE   16
#define OCT    32
#define CIN    64
#define COUT   128
#define HIN    128
#define WIN    128
#define HOUT   126
#define WOUT   126

__global__ __launch_bounds__(256, 4)
void conv_mish_bn_kernel(const float* __restrict__ x,
                         const float* __restrict__ wgt,
                         const float* __restrict__ bias,
                         const float* __restrict__ gamma,
                         const float* __restrict__ beta,
                         const float* __restrict__ rmean,
                         const float* __restrict__ rvar,
                         float* __restrict__ out)
{
    __shared__ __align__(16) float s_in[18 * 18];
    __shared__ __align__(16) float s_w[9][OCT];     // [k][oc_local], float4-readable over oc
    __shared__ float s_scale[OCT], s_shift[OCT], s_bias[OCT];

    const int tid = threadIdx.x;
    const int tx  = tid & 15;
    const int ty  = tid >> 4;

    const int tile = blockIdx.x;           // 0..63
    const int w0 = (tile & 7) * TILE;
    const int h0 = (tile >> 3) * TILE;
    const int oc0 = blockIdx.y * OCT;
    const int n   = blockIdx.z;

    if (tid < OCT) {
        const int oc = oc0 + tid;
        const float sc = gamma[oc] * rsqrtf(rvar[oc] + 1e-5f);
        s_scale[tid] = sc;
        s_shift[tid] = beta[oc] - rmean[oc] * sc;
        s_bias[tid]  = bias[oc];
    }

    float acc[OCT];
#pragma unroll
    for (int i = 0; i < OCT; i++) acc[i] = 0.0f;

    const float* xn = x + (size_t)n * CIN * HIN * WIN;

    for (int ic = 0; ic < CIN; ic++) {
        __syncthreads();   // previous iter's smem reads done (also orders s_scale init)

        // Stage 18x18 input patch for this ic (zero-fill out of range; those
        // values only feed invalid output pixels anyway).
        const float* xi = xn + (size_t)ic * HIN * WIN;
        for (int i = tid; i < 18 * 18; i += 256) {
            const int r = i / 18, c = i - r * 18;
            const int hh = h0 + r, ww = w0 + c;
            float v = 0.0f;
            if (hh < HIN && ww < WIN) v = xi[hh * WIN + ww];
            s_in[i] = v;
        }
        // Stage weights: 32 oc x 9 taps for this ic, transposed to [k][oc].
        for (int i = tid; i < OCT * 9; i += 256) {
            const int ocl = i / 9, k = i - ocl * 9;
            s_w[k][ocl] = wgt[((size_t)(oc0 + ocl) * CIN + ic) * 9 + k];
        }
        __syncthreads();

        // Per-thread 3x3 window in registers.
        float xv[9];
#pragma unroll
        for (int kh = 0; kh < 3; kh++)
#pragma unroll
            for (int kw = 0; kw < 3; kw++)
                xv[kh * 3 + kw] = s_in[(ty + kh) * 18 + (tx + kw)];

        // 288 FMAs; weights broadcast via float4 (no bank conflicts: all
        // lanes read the same address).
#pragma unroll
        for (int og = 0; og < OCT / 4; og++) {
#pragma unroll
            for (int k = 0; k < 9; k++) {
                const float4 wv = *(const float4*)&s_w[k][og * 4];
                acc[og * 4 + 0] = fmaf(xv[k], wv.x, acc[og * 4 + 0]);
                acc[og * 4 + 1] = fmaf(xv[k], wv.y, acc[og * 4 + 1]);
                acc[og * 4 + 2] = fmaf(xv[k], wv.z, acc[og * 4 + 2]);
                acc[og * 4 + 3] = fmaf(xv[k], wv.w, acc[og * 4 + 3]);
            }
        }
    }

    // Epilogue: bias + mish + BN affine, coalesced stores along w.
    const int oh = h0 + ty, ow = w0 + tx;
    if (oh < HOUT && ow < WOUT) {
        const size_t base = (((size_t)n * COUT + oc0) * HOUT + oh) * WOUT + ow;
#pragma unroll
        for (int oc = 0; oc < OCT; oc++) {
            const float z = acc[oc] + s_bias[oc];
            // softplus with overflow guard (z>15 -> softplus(z)==z in fp32)
            float sp;
            if (z > 15.0f) sp = z;
            else           sp = __logf(1.0f + __expf(z));
            float t;
            asm("tanh.approx.f32 %0, %1;" : "=f"(t) : "f"(sp));
            const float m = z * t;
            out[base + (size_t)oc * (HOUT * WOUT)] = fmaf(m, s_scale[oc], s_shift[oc]);
        }
    }
}

extern "C" void kernel_launch(void* const* d_in, const int* in_sizes, int n_in,
                              void* d_out, int out_size)
{
    const float* x     = (const float*)d_in[0];
    const float* wgt   = (const float*)d_in[1];
    const float* bias  = (const float*)d_in[2];
    const float* gamma = (const float*)d_in[3];
    const float* beta  = (const float*)d_in[4];
    const float* rmean = (const float*)d_in[5];
    const float* rvar  = (const float*)d_in[6];
    float* out = (float*)d_out;

    dim3 grid(64, COUT / OCT, 32);   // (spatial tiles, oc groups, N)
    dim3 block(256);
    conv_mish_bn_kernel<<<grid, block>>>(x, wgt, bias, gamma, beta, rmean, rvar, out);
}

// round 3
// speedup vs baseline: 4.0678x; 4.0678x over previous
#include <cuda_runtime.h>
#include <cuda_bf16.h>
#include <cstdint>

// Fused conv3x3-VALID + bias + mish + BN(inference) via implicit GEMM on
// legacy tensor cores (mma.sync m16n8k16 bf16, valid on plain sm_103).
// fp32 emulated as bf16 split-2 (hi+lo): D += Ah*Bh + Ah*Bl + Al*Bh.
// Per CTA: one (n,h) output row. M=128 px, N=128 oc, K=9 taps x 64 ic.

#define HIN   128
#define WIN   128
#define CINC  64
#define COUTC 128
#define HOUTC 126
#define WOUTC 126
#define NBATCH 32

// ---------------- device scratch ----------------
__device__ __align__(16) __nv_bfloat16 g_xhi[NBATCH * HIN * WIN * CINC];  // NHWC
__device__ __align__(16) __nv_bfloat16 g_xlo[NBATCH * HIN * WIN * CINC];
__device__ __align__(16) __nv_bfloat16 g_bhi[9 * COUTC * CINC];           // [tap][oc][ic]
__device__ __align__(16) __nv_bfloat16 g_blo[9 * COUTC * CINC];

// ---------------- helpers ----------------
__device__ __forceinline__ uint32_t smem_u32(const void* p) {
    uint32_t a;
    asm("{ .reg .u64 t; cvta.to.shared.u64 t, %1; cvt.u32.u64 %0, t; }" : "=r"(a) : "l"(p));
    return a;
}
#define SW128(o) ((o) ^ (((o) >> 3) & 0x70))

#define CP_ASYNC16(dst, src) \
    asm volatile("cp.async.cg.shared.global [%0], [%1], 16;" :: "r"(dst), "l"(src) : "memory")
#define CP_COMMIT() asm volatile("cp.async.commit_group;" ::: "memory")
#define CP_WAIT0()  asm volatile("cp.async.wait_group 0;" ::: "memory")

__device__ __forceinline__ void ldsm_x4(uint32_t addr, uint32_t* r) {
    asm volatile("ldmatrix.sync.aligned.m8n8.x4.shared.b16 {%0,%1,%2,%3}, [%4];"
        : "=r"(r[0]), "=r"(r[1]), "=r"(r[2]), "=r"(r[3]) : "r"(addr));
}
__device__ __forceinline__ void mma_bf16(float* d, const uint32_t* a,
                                         uint32_t b0, uint32_t b1) {
    asm volatile("mma.sync.aligned.m16n8k16.row.col.f32.bf16.bf16.f32 "
        "{%0,%1,%2,%3}, {%4,%5,%6,%7}, {%8,%9}, {%0,%1,%2,%3};"
        : "+f"(d[0]), "+f"(d[1]), "+f"(d[2]), "+f"(d[3])
        : "r"(a[0]), "r"(a[1]), "r"(a[2]), "r"(a[3]), "r"(b0), "r"(b1));
}

// ---------------- prepass: weights OIHW fp32 -> [tap][oc][ic] bf16 hi/lo ----
__global__ void wprep_kernel(const float* __restrict__ wgt) {
    int i = blockIdx.x * 256 + threadIdx.x;
    if (i >= 9 * COUTC * CINC) return;
    int oc = i / (9 * CINC);
    int j  = i - oc * (9 * CINC);
    int t  = j >> 6;
    int ic = j & 63;
    float f = wgt[oc * 576 + ic * 9 + t];
    __nv_bfloat16 hi = __float2bfloat16(f);
    __nv_bfloat16 lo = __float2bfloat16(f - __bfloat162float(hi));
    g_bhi[(t * COUTC + oc) * CINC + ic] = hi;
    g_blo[(t * COUTC + oc) * CINC + ic] = lo;
}

// ---------------- prepass: x NCHW fp32 -> NHWC bf16 hi/lo ----------------
__global__ void xprep_kernel(const float* __restrict__ x) {
    __shared__ float s[CINC][129];
    const int h = blockIdx.x, n = blockIdx.y, tid = threadIdx.x;
    for (int i = tid; i < CINC * WIN; i += 256) {
        int ic = i >> 7, w = i & 127;
        s[ic][w] = x[(((n * CINC) + ic) * HIN + h) * WIN + w];
    }
    __syncthreads();
    const int outbase = ((n * HIN + h) * WIN) * CINC;
    for (int j = tid; j < WIN * 8; j += 256) {
        int w = j >> 3, icg = j & 7;
        __align__(16) __nv_bfloat16 hi8[8];
        __align__(16) __nv_bfloat16 lo8[8];
#pragma unroll
        for (int u = 0; u < 8; u++) {
            float f = s[icg * 8 + u][w];
            __nv_bfloat16 hb = __float2bfloat16(f);
            hi8[u] = hb;
            lo8[u] = __float2bfloat16(f - __bfloat162float(hb));
        }
        *(uint4*)(g_xhi + outbase + w * CINC + icg * 8) = *(uint4*)hi8;
        *(uint4*)(g_xlo + outbase + w * CINC + icg * 8) = *(uint4*)lo8;
    }
}

// ---------------- main kernel ----------------
// smem: params(2048) | A: 6 x 16KB (row0 hi, row0 lo, row1 hi, ...) | B: 2 x 32KB
#define SM_PAR 0
#define SM_A   2048
#define SM_B   (SM_A + 6 * 16384)
#define SMEM_TOTAL (SM_B + 2 * 32768)

__global__ __launch_bounds__(256, 1)
void conv_hmma_kernel(const float* __restrict__ bias,
                      const float* __restrict__ gamma,
                      const float* __restrict__ beta,
                      const float* __restrict__ rmean,
                      const float* __restrict__ rvar,
                      float* __restrict__ out)
{
    extern __shared__ char smem[];
    const uint32_t sbase = smem_u32(smem);
    const int tid = threadIdx.x, lane = tid & 31, wid = tid >> 5;
    const int h = blockIdx.x, n = blockIdx.y;

    if (tid < COUTC) {
        const float sc = gamma[tid] * rsqrtf(rvar[tid] + 1e-5f);
        ((float*)(smem + SM_PAR))[tid]        = bias[tid];
        ((float*)(smem + SM_PAR + 512))[tid]  = sc;
        ((float*)(smem + SM_PAR + 1024))[tid] = beta[tid] - rmean[tid] * sc;
    }

    // --- stage A: 3 input rows (h..h+2), hi+lo, SW128-swizzled, via cp.async ---
#pragma unroll
    for (int k = 0; k < 24; k++) {
        const int idx  = tid + k * 256;       // 0..6143
        const int tile = idx >> 10;           // 0..5
        const int wit  = idx & 1023;
        const int r = wit >> 3, c = wit & 7;  // pixel w, 16B chunk
        const int rr = tile >> 1, v = tile & 1;
        const __nv_bfloat16* src = (v ? g_xlo : g_xhi) +
            (((n * HIN + (h + rr)) * WIN) + r) * CINC + c * 8;
        const uint32_t dst = sbase + SM_A + tile * 16384 +
                             SW128((uint32_t)(r * 128 + c * 16));
        CP_ASYNC16(dst, src);
    }
    // --- stage B tap 0 ---
#pragma unroll
    for (int k = 0; k < 8; k++) {
        const int idx = tid + k * 256;        // 0..2047
        const int v = idx >> 10;
        const int wit = idx & 1023;
        const int r = wit >> 3, c = wit & 7;  // oc, chunk
        const __nv_bfloat16* src = (v ? g_blo : g_bhi) + r * CINC + c * 8;
        const uint32_t dst = sbase + SM_B + v * 16384 +
                             SW128((uint32_t)(r * 128 + c * 16));
        CP_ASYNC16(dst, src);
    }
    CP_COMMIT();
    CP_WAIT0();
    __syncthreads();

    const int m0 = (wid & 1) * 64;    // warp rows (pixels)
    const int n0 = (wid >> 1) * 32;   // warp cols (oc)
    float acc[4][4][4];
#pragma unroll
    for (int i = 0; i < 4; i++)
#pragma unroll
        for (int j = 0; j < 4; j++)
#pragma unroll
            for (int e = 0; e < 4; e++) acc[i][j][e] = 0.0f;

    for (int t = 0; t < 9; t++) {
        const int b = t & 1;
        if (t < 8) {  // prefetch next tap's B into other buffer
            const int tn = t + 1;
#pragma unroll
            for (int k = 0; k < 8; k++) {
                const int idx = tid + k * 256;
                const int v = idx >> 10;
                const int wit = idx & 1023;
                const int r = wit >> 3, c = wit & 7;
                const __nv_bfloat16* src = (v ? g_blo : g_bhi) +
                    (tn * COUTC + r) * CINC + c * 8;
                const uint32_t dst = sbase + SM_B + (b ^ 1) * 32768 + v * 16384 +
                                     SW128((uint32_t)(r * 128 + c * 16));
                CP_ASYNC16(dst, src);
            }
            CP_COMMIT();
        }

        const int kh = t / 3, kw = t - kh * 3;
        const uint32_t aHi = sbase + SM_A + (kh * 2 + 0) * 16384;
        const uint32_t aLo = sbase + SM_A + (kh * 2 + 1) * 16384;
        const uint32_t bHi = sbase + SM_B + b * 32768;
        const uint32_t bLo = bHi + 16384;

#pragma unroll
        for (int ks = 0; ks < 4; ks++) {
            uint32_t ah[4][4], al[4][4];
#pragma unroll
            for (int i = 0; i < 4; i++) {
                const int row = m0 + i * 16 + (lane & 15) + kw;
                const uint32_t off =
                    SW128((uint32_t)(row * 128 + (ks * 2 + (lane >> 4)) * 16));
                ldsm_x4(aHi + off, ah[i]);
                ldsm_x4(aLo + off, al[i]);
            }
            uint32_t bh[8], bl[8];
#pragma unroll
            for (int jj = 0; jj < 2; jj++) {
                const int quad = lane >> 3;
                const int row = n0 + jj * 16 + (quad >> 1) * 8 + (lane & 7);
                const uint32_t off =
                    SW128((uint32_t)(row * 128 + (ks * 2 + (quad & 1)) * 16));
                ldsm_x4(bHi + off, &bh[jj * 4]);
                ldsm_x4(bLo + off, &bl[jj * 4]);
            }
#pragma unroll
            for (int i = 0; i < 4; i++)
#pragma unroll
                for (int j = 0; j < 4; j++) {
                    mma_bf16(acc[i][j], ah[i], bh[j * 2], bh[j * 2 + 1]);
                    mma_bf16(acc[i][j], ah[i], bl[j * 2], bl[j * 2 + 1]);
                    mma_bf16(acc[i][j], al[i], bh[j * 2], bh[j * 2 + 1]);
                }
        }

        if (t < 8) CP_WAIT0();
        __syncthreads();
    }

    // --- epilogue: bias + mish + BN, write from fragments ---
    const float* s_bias  = (const float*)(smem + SM_PAR);
    const float* s_scale = (const float*)(smem + SM_PAR + 512);
    const float* s_shift = (const float*)(smem + SM_PAR + 1024);

#pragma unroll
    for (int i = 0; i < 4; i++)
#pragma unroll
        for (int j = 0; j < 4; j++)
#pragma unroll
            for (int e = 0; e < 4; e++) {
                const int w  = m0 + i * 16 + (lane >> 2) + ((e & 2) ? 8 : 0);
                const int oc = n0 + j * 8 + (lane & 3) * 2 + (e & 1);
                if (w < WOUTC) {
                    const float z = acc[i][j][e] + s_bias[oc];
                    float sp;
                    if (z > 15.0f) sp = z;
                    else           sp = __logf(1.0f + __expf(z));
                    float th;
                    asm("tanh.approx.f32 %0, %1;" : "=f"(th) : "f"(sp));
                    out[(((size_t)n * COUTC + oc) * HOUTC + h) * WOUTC + w] =
                        fmaf(z * th, s_scale[oc], s_shift[oc]);
                }
            }
}

// ---------------- launch ----------------
extern "C" void kernel_launch(void* const* d_in, const int* in_sizes, int n_in,
                              void* d_out, int out_size)
{
    const float* x     = (const float*)d_in[0];
    const float* wgt   = (const float*)d_in[1];
    const float* bias  = (const float*)d_in[2];
    const float* gamma = (const float*)d_in[3];
    const float* beta  = (const float*)d_in[4];
    const float* rmean = (const float*)d_in[5];
    const float* rvar  = (const float*)d_in[6];
    float* out = (float*)d_out;

    cudaFuncSetAttribute(conv_hmma_kernel,
                         cudaFuncAttributeMaxDynamicSharedMemorySize, SMEM_TOTAL);

    wprep_kernel<<<(9 * COUTC * CINC + 255) / 256, 256>>>(wgt);
    xprep_kernel<<<dim3(HIN, NBATCH), 256>>>(x);
    conv_hmma_kernel<<<dim3(HOUTC, NBATCH), 256, SMEM_TOTAL>>>(bias, gamma, beta,
                                                               rmean, rvar, out);
}

// round 4
// speedup vs baseline: 5.0852x; 1.2501x over previous
#include <cuda_runtime.h>
#include <cuda_fp16.h>
#include <cstdint>

// Fused conv3x3-VALID + bias + mish + BN(inference), implicit GEMM on
// mma.sync m16n8k16 fp16 (plain sm_103 compatible).
// Precision: x kept as single fp16 (err ~2^-11); weights split fp16 hi+lo.
// D += Ah*Bh + Ah*Bl  -> total rel err ~1.5e-4 << 1e-3 threshold.
// Per CTA: one (n,h) output row. M=128 px, N=128 oc, K=9 taps x 64 ic.

#define HIN   128
#define WIN   128
#define CINC  64
#define COUTC 128
#define HOUTC 126
#define WOUTC 126
#define NBATCH 32

// ---------------- device scratch ----------------
__device__ __align__(16) __half g_xh [NBATCH * HIN * WIN * CINC];  // NHWC fp16
__device__ __align__(16) __half g_bhi[9 * COUTC * CINC];           // [tap][oc][ic]
__device__ __align__(16) __half g_blo[9 * COUTC * CINC];

// ---------------- helpers ----------------
__device__ __forceinline__ uint32_t smem_u32(const void* p) {
    uint32_t a;
    asm("{ .reg .u64 t; cvta.to.shared.u64 t, %1; cvt.u32.u64 %0, t; }" : "=r"(a) : "l"(p));
    return a;
}
#define SW128(o) ((o) ^ (((o) >> 3) & 0x70))

#define CP_ASYNC16(dst, src) \
    asm volatile("cp.async.cg.shared.global [%0], [%1], 16;" :: "r"(dst), "l"(src) : "memory")
#define CP_COMMIT() asm volatile("cp.async.commit_group;" ::: "memory")
#define CP_WAIT0()  asm volatile("cp.async.wait_group 0;" ::: "memory")

__device__ __forceinline__ void ldsm_x4(uint32_t addr, uint32_t* r) {
    asm volatile("ldmatrix.sync.aligned.m8n8.x4.shared.b16 {%0,%1,%2,%3}, [%4];"
        : "=r"(r[0]), "=r"(r[1]), "=r"(r[2]), "=r"(r[3]) : "r"(addr));
}
__device__ __forceinline__ void mma_fp16(float* d, const uint32_t* a,
                                         uint32_t b0, uint32_t b1) {
    asm volatile("mma.sync.aligned.m16n8k16.row.col.f32.f16.f16.f32 "
        "{%0,%1,%2,%3}, {%4,%5,%6,%7}, {%8,%9}, {%0,%1,%2,%3};"
        : "+f"(d[0]), "+f"(d[1]), "+f"(d[2]), "+f"(d[3])
        : "r"(a[0]), "r"(a[1]), "r"(a[2]), "r"(a[3]), "r"(b0), "r"(b1));
}

// ---------------- prepass: weights OIHW fp32 -> [tap][oc][ic] fp16 hi/lo ---
__global__ void wprep_kernel(const float* __restrict__ wgt) {
    int i = blockIdx.x * 256 + threadIdx.x;
    if (i >= 9 * COUTC * CINC) return;
    int oc = i / (9 * CINC);
    int j  = i - oc * (9 * CINC);
    int t  = j >> 6;
    int ic = j & 63;
    float f = wgt[oc * 576 + ic * 9 + t];
    __half hi = __float2half(f);
    __half lo = __float2half(f - __half2float(hi));
    g_bhi[(t * COUTC + oc) * CINC + ic] = hi;
    g_blo[(t * COUTC + oc) * CINC + ic] = lo;
}

// ---------------- prepass: x NCHW fp32 -> NHWC fp16 ----------------
__global__ void xprep_kernel(const float* __restrict__ x) {
    __shared__ float s[CINC][129];
    const int h = blockIdx.x, n = blockIdx.y, tid = threadIdx.x;
    for (int i = tid; i < CINC * WIN; i += 256) {
        int ic = i >> 7, w = i & 127;
        s[ic][w] = x[(((n * CINC) + ic) * HIN + h) * WIN + w];
    }
    __syncthreads();
    const int outbase = ((n * HIN + h) * WIN) * CINC;
    for (int j = tid; j < WIN * 8; j += 256) {
        int w = j >> 3, icg = j & 7;
        __align__(16) __half h8[8];
#pragma unroll
        for (int u = 0; u < 8; u++) h8[u] = __float2half(s[icg * 8 + u][w]);
        *(uint4*)(g_xh + outbase + w * CINC + icg * 8) = *(uint4*)h8;
    }
}

// ---------------- main kernel ----------------
// smem: params(1536) | A: 3 x 16KB (rows h..h+2) | B: 2 x 32KB (hi+lo, dbl buf)
#define SM_PAR 0
#define SM_A   2048
#define SM_B   (SM_A + 3 * 16384)
#define SMEM_TOTAL (SM_B + 2 * 32768)

__global__ __launch_bounds__(256, 1)
void conv_hmma_kernel(const float* __restrict__ bias,
                      const float* __restrict__ gamma,
                      const float* __restrict__ beta,
                      const float* __restrict__ rmean,
                      const float* __restrict__ rvar,
                      float* __restrict__ out)
{
    extern __shared__ char smem[];
    const uint32_t sbase = smem_u32(smem);
    const int tid = threadIdx.x, lane = tid & 31, wid = tid >> 5;
    const int h = blockIdx.x, n = blockIdx.y;

    if (tid < COUTC) {
        const float sc = gamma[tid] * rsqrtf(rvar[tid] + 1e-5f);
        ((float*)(smem + SM_PAR))[tid]        = bias[tid];
        ((float*)(smem + SM_PAR + 512))[tid]  = sc;
        ((float*)(smem + SM_PAR + 1024))[tid] = beta[tid] - rmean[tid] * sc;
    }

    // --- stage A: 3 input rows (h..h+2) fp16, SW128-swizzled, via cp.async ---
#pragma unroll
    for (int k = 0; k < 12; k++) {
        const int idx  = tid + k * 256;       // 0..3071
        const int tile = idx >> 10;           // 0..2 (input row)
        const int wit  = idx & 1023;
        const int r = wit >> 3, c = wit & 7;  // pixel w, 16B chunk
        const __half* src = g_xh + (((n * HIN + (h + tile)) * WIN) + r) * CINC + c * 8;
        const uint32_t dst = sbase + SM_A + tile * 16384 +
                             SW128((uint32_t)(r * 128 + c * 16));
        CP_ASYNC16(dst, src);
    }
    // --- stage B tap 0 (hi then lo) ---
#pragma unroll
    for (int k = 0; k < 8; k++) {
        const int idx = tid + k * 256;        // 0..2047
        const int v = idx >> 10;
        const int wit = idx & 1023;
        const int r = wit >> 3, c = wit & 7;  // oc, chunk
        const __half* src = (v ? g_blo : g_bhi) + r * CINC + c * 8;
        const uint32_t dst = sbase + SM_B + v * 16384 +
                             SW128((uint32_t)(r * 128 + c * 16));
        CP_ASYNC16(dst, src);
    }
    CP_COMMIT();
    CP_WAIT0();
    __syncthreads();

    const int m0 = (wid & 1) * 64;    // warp rows (pixels)
    const int n0 = (wid >> 1) * 32;   // warp cols (oc)
    float acc[4][4][4];
#pragma unroll
    for (int i = 0; i < 4; i++)
#pragma unroll
        for (int j = 0; j < 4; j++)
#pragma unroll
            for (int e = 0; e < 4; e++) acc[i][j][e] = 0.0f;

    for (int t = 0; t < 9; t++) {
        const int b = t & 1;
        if (t < 8) {  // prefetch next tap's B into other buffer
            const int tn = t + 1;
#pragma unroll
            for (int k = 0; k < 8; k++) {
                const int idx = tid + k * 256;
                const int v = idx >> 10;
                const int wit = idx & 1023;
                const int r = wit >> 3, c = wit & 7;
                const __half* src = (v ? g_blo : g_bhi) +
                    (tn * COUTC + r) * CINC + c * 8;
                const uint32_t dst = sbase + SM_B + (b ^ 1) * 32768 + v * 16384 +
                                     SW128((uint32_t)(r * 128 + c * 16));
                CP_ASYNC16(dst, src);
            }
            CP_COMMIT();
        }

        const int kh = t / 3, kw = t - kh * 3;
        const uint32_t aT  = sbase + SM_A + kh * 16384;
        const uint32_t bHi = sbase + SM_B + b * 32768;
        const uint32_t bLo = bHi + 16384;

#pragma unroll
        for (int ks = 0; ks < 4; ks++) {
            uint32_t ah[4][4];
#pragma unroll
            for (int i = 0; i < 4; i++) {
                const int row = m0 + i * 16 + (lane & 15) + kw;
                const uint32_t off =
                    SW128((uint32_t)(row * 128 + (ks * 2 + (lane >> 4)) * 16));
                ldsm_x4(aT + off, ah[i]);
            }
            uint32_t bh[8], bl[8];
#pragma unroll
            for (int jj = 0; jj < 2; jj++) {
                const int quad = lane >> 3;
                const int row = n0 + jj * 16 + (quad >> 1) * 8 + (lane & 7);
                const uint32_t off =
                    SW128((uint32_t)(row * 128 + (ks * 2 + (quad & 1)) * 16));
                ldsm_x4(bHi + off, &bh[jj * 4]);
                ldsm_x4(bLo + off, &bl[jj * 4]);
            }
            // hi pass then lo pass: acc reuse distance = 16 MMAs (no RAW stall)
#pragma unroll
            for (int i = 0; i < 4; i++)
#pragma unroll
                for (int j = 0; j < 4; j++)
                    mma_fp16(acc[i][j], ah[i], bh[j * 2], bh[j * 2 + 1]);
#pragma unroll
            for (int i = 0; i < 4; i++)
#pragma unroll
                for (int j = 0; j < 4; j++)
                    mma_fp16(acc[i][j], ah[i], bl[j * 2], bl[j * 2 + 1]);
        }

        if (t < 8) CP_WAIT0();
        __syncthreads();
    }

    // --- epilogue: bias + mish + BN, write from fragments ---
    const float* s_bias  = (const float*)(smem + SM_PAR);
    const float* s_scale = (const float*)(smem + SM_PAR + 512);
    const float* s_shift = (const float*)(smem + SM_PAR + 1024);

#pragma unroll
    for (int i = 0; i < 4; i++)
#pragma unroll
        for (int j = 0; j < 4; j++)
#pragma unroll
            for (int e = 0; e < 4; e++) {
                const int w  = m0 + i * 16 + (lane >> 2) + ((e & 2) ? 8 : 0);
                const int oc = n0 + j * 8 + (lane & 3) * 2 + (e & 1);
                if (w < WOUTC) {
                    const float z = acc[i][j][e] + s_bias[oc];
                    float sp;
                    if (z > 15.0f) sp = z;
                    else           sp = __logf(1.0f + __expf(z));
                    float th;
                    asm("tanh.approx.f32 %0, %1;" : "=f"(th) : "f"(sp));
                    out[(((size_t)n * COUTC + oc) * HOUTC + h) * WOUTC + w] =
                        fmaf(z * th, s_scale[oc], s_shift[oc]);
                }
            }
}

// ---------------- launch ----------------
extern "C" void kernel_launch(void* const* d_in, const int* in_sizes, int n_in,
                              void* d_out, int out_size)
{
    const float* x     = (const float*)d_in[0];
    const float* wgt   = (const float*)d_in[1];
    const float* bias  = (const float*)d_in[2];
    const float* gamma = (const float*)d_in[3];
    const float* beta  = (const float*)d_in[4];
    const float* rmean = (const float*)d_in[5];
    const float* rvar  = (const float*)d_in[6];
    float* out = (float*)d_out;

    cudaFuncSetAttribute(conv_hmma_kernel,
                         cudaFuncAttributeMaxDynamicSharedMemorySize, SMEM_TOTAL);

    wprep_kernel<<<(9 * COUTC * CINC + 255) / 256, 256>>>(wgt);
    xprep_kernel<<<dim3(HIN, NBATCH), 256>>>(x);
    conv_hmma_kernel<<<dim3(HOUTC, NBATCH), 256, SMEM_TOTAL>>>(bias, gamma, beta,
                                                               rmean, rvar, out);
}

// round 5
// speedup vs baseline: 5.6827x; 1.1175x over previous
#include <cuda_runtime.h>
#include <cuda_fp16.h>
#include <cstdint>

// Fused conv3x3-VALID + bias + mish + BN(inference), implicit GEMM on
// mma.sync m16n8k16 fp16. x as fp16, weights split fp16 hi+lo.
// Per CTA: TWO (n,h) output rows. M=256 px, N=128 oc, K=9 taps x 64 ic.

#define HIN   128
#define WIN   128
#define CINC  64
#define COUTC 128
#define HOUTC 126
#define WOUTC 126
#define NBATCH 32

__device__ __align__(16) __half g_xh [NBATCH * HIN * WIN * CINC];  // NHWC fp16
__device__ __align__(16) __half g_bhi[9 * COUTC * CINC];           // [tap][oc][ic]
__device__ __align__(16) __half g_blo[9 * COUTC * CINC];

__device__ __forceinline__ uint32_t smem_u32(const void* p) {
    uint32_t a;
    asm("{ .reg .u64 t; cvta.to.shared.u64 t, %1; cvt.u32.u64 %0, t; }" : "=r"(a) : "l"(p));
    return a;
}
#define SW128(o) ((o) ^ (((o) >> 3) & 0x70))

#define CP_ASYNC16(dst, src) \
    asm volatile("cp.async.cg.shared.global [%0], [%1], 16;" :: "r"(dst), "l"(src) : "memory")
#define CP_COMMIT() asm volatile("cp.async.commit_group;" ::: "memory")
#define CP_WAIT0()  asm volatile("cp.async.wait_group 0;" ::: "memory")

__device__ __forceinline__ void ldsm_x4(uint32_t addr, uint32_t* r) {
    asm volatile("ldmatrix.sync.aligned.m8n8.x4.shared.b16 {%0,%1,%2,%3}, [%4];"
        : "=r"(r[0]), "=r"(r[1]), "=r"(r[2]), "=r"(r[3]) : "r"(addr));
}
__device__ __forceinline__ void mma_fp16(float* d, const uint32_t* a,
                                         uint32_t b0, uint32_t b1) {
    asm volatile("mma.sync.aligned.m16n8k16.row.col.f32.f16.f16.f32 "
        "{%0,%1,%2,%3}, {%4,%5,%6,%7}, {%8,%9}, {%0,%1,%2,%3};"
        : "+f"(d[0]), "+f"(d[1]), "+f"(d[2]), "+f"(d[3])
        : "r"(a[0]), "r"(a[1]), "r"(a[2]), "r"(a[3]), "r"(b0), "r"(b1));
}

// ---------------- prepass: weights OIHW fp32 -> [tap][oc][ic] fp16 hi/lo ---
__global__ void wprep_kernel(const float* __restrict__ wgt) {
    int i = blockIdx.x * 256 + threadIdx.x;
    if (i >= 9 * COUTC * CINC) return;
    int oc = i / (9 * CINC);
    int j  = i - oc * (9 * CINC);
    int t  = j >> 6;
    int ic = j & 63;
    float f = wgt[oc * 576 + ic * 9 + t];
    __half hi = __float2half(f);
    __half lo = __float2half(f - __half2float(hi));
    g_bhi[(t * COUTC + oc) * CINC + ic] = hi;
    g_blo[(t * COUTC + oc) * CINC + ic] = lo;
}

// ---------------- prepass: x NCHW fp32 -> NHWC fp16 ----------------
__global__ void xprep_kernel(const float* __restrict__ x) {
    __shared__ float s[CINC][129];
    const int h = blockIdx.x, n = blockIdx.y, tid = threadIdx.x;
    for (int i = tid; i < CINC * WIN; i += 256) {
        int ic = i >> 7, w = i & 127;
        s[ic][w] = x[(((n * CINC) + ic) * HIN + h) * WIN + w];
    }
    __syncthreads();
    const int outbase = ((n * HIN + h) * WIN) * CINC;
    for (int j = tid; j < WIN * 8; j += 256) {
        int w = j >> 3, icg = j & 7;
        __align__(16) __half h8[8];
#pragma unroll
        for (int u = 0; u < 8; u++) h8[u] = __float2half(s[icg * 8 + u][w]);
        *(uint4*)(g_xh + outbase + w * CINC + icg * 8) = *(uint4*)h8;
    }
}

// ---------------- main kernel ----------------
// smem: params(2048) | A: 4 x 16KB (input rows h0..h0+3) | B: 2 x 32KB dbl buf
#define SM_PAR 0
#define SM_A   2048
#define SM_B   (SM_A + 4 * 16384)
#define SMEM_TOTAL (SM_B + 2 * 32768)

__global__ __launch_bounds__(256, 1)
void conv_hmma_kernel(const float* __restrict__ bias,
                      const float* __restrict__ gamma,
                      const float* __restrict__ beta,
                      const float* __restrict__ rmean,
                      const float* __restrict__ rvar,
                      float* __restrict__ out)
{
    extern __shared__ char smem[];
    const uint32_t sbase = smem_u32(smem);
    const int tid = threadIdx.x, lane = tid & 31, wid = tid >> 5;
    const int h0 = blockIdx.x * 2, n = blockIdx.y;

    if (tid < COUTC) {
        const float sc = gamma[tid] * rsqrtf(rvar[tid] + 1e-5f);
        ((float*)(smem + SM_PAR))[tid]        = bias[tid];
        ((float*)(smem + SM_PAR + 512))[tid]  = sc;
        ((float*)(smem + SM_PAR + 1024))[tid] = beta[tid] - rmean[tid] * sc;
    }

    // --- stage A: 4 input rows (h0..h0+3), SW128, cp.async (h0 <= 124) ---
#pragma unroll
    for (int k = 0; k < 16; k++) {
        const int idx  = tid + k * 256;       // 0..4095
        const int tile = idx >> 10;           // 0..3 (input row)
        const int wit  = idx & 1023;
        const int r = wit >> 3, c = wit & 7;  // pixel w, 16B chunk
        const __half* src = g_xh + (((n * HIN + (h0 + tile)) * WIN) + r) * CINC + c * 8;
        const uint32_t dst = sbase + SM_A + tile * 16384 +
                             SW128((uint32_t)(r * 128 + c * 16));
        CP_ASYNC16(dst, src);
    }
    // --- stage B tap 0 (hi then lo) ---
#pragma unroll
    for (int k = 0; k < 8; k++) {
        const int idx = tid + k * 256;        // 0..2047
        const int v = idx >> 10;
        const int wit = idx & 1023;
        const int r = wit >> 3, c = wit & 7;  // oc, chunk
        const __half* src = (v ? g_blo : g_bhi) + r * CINC + c * 8;
        const uint32_t dst = sbase + SM_B + v * 16384 +
                             SW128((uint32_t)(r * 128 + c * 16));
        CP_ASYNC16(dst, src);
    }
    CP_COMMIT();
    CP_WAIT0();
    __syncthreads();

    // warp tile: 64 px x 64 oc.  wrow = wid&3 -> (h_local, w-base); wid>>2 -> oc half
    const int wrow    = wid & 3;
    const int h_local = wrow >> 1;         // 0: warps 0,1 ; 1: warps 2,3
    const int mw      = (wrow & 1) * 64;   // pixel base
    const int n0      = (wid >> 2) * 64;   // oc base

    float acc[4][8][4];
#pragma unroll
    for (int i = 0; i < 4; i++)
#pragma unroll
        for (int j = 0; j < 8; j++)
#pragma unroll
            for (int e = 0; e < 4; e++) acc[i][j][e] = 0.0f;

    for (int t = 0; t < 9; t++) {
        const int b = t & 1;
        if (t < 8) {  // prefetch next tap's B
            const int tn = t + 1;
#pragma unroll
            for (int k = 0; k < 8; k++) {
                const int idx = tid + k * 256;
                const int v = idx >> 10;
                const int wit = idx & 1023;
                const int r = wit >> 3, c = wit & 7;
                const __half* src = (v ? g_blo : g_bhi) +
                    (tn * COUTC + r) * CINC + c * 8;
                const uint32_t dst = sbase + SM_B + (b ^ 1) * 32768 + v * 16384 +
                                     SW128((uint32_t)(r * 128 + c * 16));
                CP_ASYNC16(dst, src);
            }
            CP_COMMIT();
        }

        const int kh = t / 3, kw = t - kh * 3;
        const uint32_t aT  = sbase + SM_A + (h_local + kh) * 16384;
        const uint32_t bHi = sbase + SM_B + b * 32768;
        const uint32_t bLo = bHi + 16384;

#pragma unroll
        for (int ks = 0; ks < 4; ks++) {
            uint32_t ah[4][4];
#pragma unroll
            for (int i = 0; i < 4; i++) {
                // rows can reach 129 for kw=2 -> reads spill into adjacent smem;
                // those products land only in discarded outputs w>=126.
                const int row = mw + i * 16 + (lane & 15) + kw;
                const uint32_t off =
                    SW128((uint32_t)(row * 128 + (ks * 2 + (lane >> 4)) * 16));
                ldsm_x4(aT + off, ah[i]);
            }
#pragma unroll
            for (int jj = 0; jj < 4; jj++) {
                const int quad = lane >> 3;
                const int brow = n0 + jj * 16 + (quad >> 1) * 8 + (lane & 7);
                const uint32_t boff =
                    SW128((uint32_t)(brow * 128 + (ks * 2 + (quad & 1)) * 16));
                uint32_t bh[4], bl[4];
                ldsm_x4(bHi + boff, bh);
                ldsm_x4(bLo + boff, bl);
#pragma unroll
                for (int i = 0; i < 4; i++) {
                    mma_fp16(acc[i][jj * 2],     ah[i], bh[0], bh[1]);
                    mma_fp16(acc[i][jj * 2 + 1], ah[i], bh[2], bh[3]);
                }
#pragma unroll
                for (int i = 0; i < 4; i++) {
                    mma_fp16(acc[i][jj * 2],     ah[i], bl[0], bl[1]);
                    mma_fp16(acc[i][jj * 2 + 1], ah[i], bl[2], bl[3]);
                }
            }
        }

        if (t < 8) CP_WAIT0();
        __syncthreads();
    }

    // --- epilogue: bias + mish + BN ---
    const float* s_bias  = (const float*)(smem + SM_PAR);
    const float* s_scale = (const float*)(smem + SM_PAR + 512);
    const float* s_shift = (const float*)(smem + SM_PAR + 1024);
    const int h_out = h0 + h_local;                      // <= 125, always valid

#pragma unroll
    for (int i = 0; i < 4; i++)
#pragma unroll
        for (int j = 0; j < 8; j++)
#pragma unroll
            for (int e = 0; e < 4; e++) {
                const int w  = mw + i * 16 + (lane >> 2) + ((e & 2) ? 8 : 0);
                const int oc = n0 + j * 8 + (lane & 3) * 2 + (e & 1);
                if (w < WOUTC) {
                    const float z = acc[i][j][e] + s_bias[oc];
                    // mish: z*tanh(softplus(z)) = z*v/(v+2), v = e^z*(e^z+2)
                    float u;
                    asm("ex2.approx.f32 %0, %1;" : "=f"(u) : "f"(z * 1.44269504f));
                    const float v = u * (u + 2.0f);
                    float m = z * __fdividef(v, v + 2.0f);
                    if (z > 30.0f) m = z;
                    out[(((size_t)n * COUTC + oc) * HOUTC + h_out) * WOUTC + w] =
                        fmaf(m, s_scale[oc], s_shift[oc]);
                }
            }
}

// ---------------- launch ----------------
extern "C" void kernel_launch(void* const* d_in, const int* in_sizes, int n_in,
                              void* d_out, int out_size)
{
    const float* x     = (const float*)d_in[0];
    const float* wgt   = (const float*)d_in[1];
    const float* bias  = (const float*)d_in[2];
    const float* gamma = (const float*)d_in[3];
    const float* beta  = (const float*)d_in[4];
    const float* rmean = (const float*)d_in[5];
    const float* rvar  = (const float*)d_in[6];
    float* out = (float*)d_out;

    cudaFuncSetAttribute(conv_hmma_kernel,
                         cudaFuncAttributeMaxDynamicSharedMemorySize, SMEM_TOTAL);

    wprep_kernel<<<(9 * COUTC * CINC + 255) / 256, 256>>>(wgt);
    xprep_kernel<<<dim3(HIN, NBATCH), 256>>>(x);
    conv_hmma_kernel<<<dim3(HOUTC / 2, NBATCH), 256, SMEM_TOTAL>>>(bias, gamma, beta,
                                                                   rmean, rvar, out);
}

// round 6
// speedup vs baseline: 8.2789x; 1.4569x over previous
#include <cuda_runtime.h>
#include <cuda_fp16.h>
#include <cstdint>

// Fused conv3x3-VALID + bias + mish + BN(inference), implicit GEMM on
// mma.sync m16n8k16 fp16. x and weights both single fp16 (rel_err ~3e-4 < 1e-3).
// Per CTA: TWO (n,h) output rows. M=256 px, N=128 oc, K=9 taps x 64 ic.
// 512 threads / 16 warps; warp tile 64 px x 32 oc.

#define HIN   128
#define WIN   128
#define CINC  64
#define COUTC 128
#define HOUTC 126
#define WOUTC 126
#define NBATCH 32

__device__ __align__(16) __half g_xh[NBATCH * HIN * WIN * CINC];  // NHWC fp16
__device__ __align__(16) __half g_bh[9 * COUTC * CINC];           // [tap][oc][ic]

__device__ __forceinline__ uint32_t smem_u32(const void* p) {
    uint32_t a;
    asm("{ .reg .u64 t; cvta.to.shared.u64 t, %1; cvt.u32.u64 %0, t; }" : "=r"(a) : "l"(p));
    return a;
}
#define SW128(o) ((o) ^ (((o) >> 3) & 0x70))

#define CP_ASYNC16(dst, src) \
    asm volatile("cp.async.cg.shared.global [%0], [%1], 16;" :: "r"(dst), "l"(src) : "memory")
#define CP_COMMIT() asm volatile("cp.async.commit_group;" ::: "memory")
#define CP_WAIT0()  asm volatile("cp.async.wait_group 0;" ::: "memory")

__device__ __forceinline__ void ldsm_x4(uint32_t addr, uint32_t* r) {
    asm volatile("ldmatrix.sync.aligned.m8n8.x4.shared.b16 {%0,%1,%2,%3}, [%4];"
        : "=r"(r[0]), "=r"(r[1]), "=r"(r[2]), "=r"(r[3]) : "r"(addr));
}
__device__ __forceinline__ void mma_fp16(float* d, const uint32_t* a,
                                         uint32_t b0, uint32_t b1) {
    asm volatile("mma.sync.aligned.m16n8k16.row.col.f32.f16.f16.f32 "
        "{%0,%1,%2,%3}, {%4,%5,%6,%7}, {%8,%9}, {%0,%1,%2,%3};"
        : "+f"(d[0]), "+f"(d[1]), "+f"(d[2]), "+f"(d[3])
        : "r"(a[0]), "r"(a[1]), "r"(a[2]), "r"(a[3]), "r"(b0), "r"(b1));
}

// ---------------- prepass: weights OIHW fp32 -> [tap][oc][ic] fp16 --------
__global__ void wprep_kernel(const float* __restrict__ wgt) {
    int i = blockIdx.x * 256 + threadIdx.x;
    if (i >= 9 * COUTC * CINC) return;
    int oc = i / (9 * CINC);
    int j  = i - oc * (9 * CINC);
    int t  = j >> 6;
    int ic = j & 63;
    g_bh[(t * COUTC + oc) * CINC + ic] = __float2half(wgt[oc * 576 + ic * 9 + t]);
}

// ---------------- prepass: x NCHW fp32 -> NHWC fp16 ----------------
__global__ void xprep_kernel(const float* __restrict__ x) {
    __shared__ float s[CINC][129];
    const int h = blockIdx.x, n = blockIdx.y, tid = threadIdx.x;
    for (int i = tid; i < CINC * WIN; i += 256) {
        int ic = i >> 7, w = i & 127;
        s[ic][w] = x[(((n * CINC) + ic) * HIN + h) * WIN + w];
    }
    __syncthreads();
    const int outbase = ((n * HIN + h) * WIN) * CINC;
    for (int j = tid; j < WIN * 8; j += 256) {
        int w = j >> 3, icg = j & 7;
        __align__(16) __half h8[8];
#pragma unroll
        for (int u = 0; u < 8; u++) h8[u] = __float2half(s[icg * 8 + u][w]);
        *(uint4*)(g_xh + outbase + w * CINC + icg * 8) = *(uint4*)h8;
    }
}

// ---------------- main kernel ----------------
// smem: params(2048) | A: 4 x 16KB (input rows h0..h0+3) | B: 2 x 16KB dbl buf
#define SM_PAR 0
#define SM_A   2048
#define SM_B   (SM_A + 4 * 16384)
#define SMEM_TOTAL (SM_B + 2 * 16384)

__global__ __launch_bounds__(512, 1)
void conv_hmma_kernel(const float* __restrict__ bias,
                      const float* __restrict__ gamma,
                      const float* __restrict__ beta,
                      const float* __restrict__ rmean,
                      const float* __restrict__ rvar,
                      float* __restrict__ out)
{
    extern __shared__ char smem[];
    const uint32_t sbase = smem_u32(smem);
    const int tid = threadIdx.x, lane = tid & 31, wid = tid >> 5;
    const int h0 = blockIdx.x * 2, n = blockIdx.y;

    if (tid < COUTC) {
        const float sc = gamma[tid] * rsqrtf(rvar[tid] + 1e-5f);
        ((float*)(smem + SM_PAR))[tid]        = bias[tid];
        ((float*)(smem + SM_PAR + 512))[tid]  = sc;
        ((float*)(smem + SM_PAR + 1024))[tid] = beta[tid] - rmean[tid] * sc;
    }

    // --- stage A: 4 input rows (h0..h0+3), SW128, cp.async ---
#pragma unroll
    for (int k = 0; k < 8; k++) {
        const int idx  = tid + k * 512;       // 0..4095
        const int tile = idx >> 10;           // input row 0..3
        const int wit  = idx & 1023;
        const int r = wit >> 3, c = wit & 7;  // pixel w, 16B chunk
        const __half* src = g_xh + (((n * HIN + (h0 + tile)) * WIN) + r) * CINC + c * 8;
        const uint32_t dst = sbase + SM_A + tile * 16384 +
                             SW128((uint32_t)(r * 128 + c * 16));
        CP_ASYNC16(dst, src);
    }
    // --- stage B tap 0 ---
#pragma unroll
    for (int k = 0; k < 2; k++) {
        const int idx = tid + k * 512;        // 0..1023
        const int r = idx >> 3, c = idx & 7;  // oc, chunk
        const __half* src = g_bh + r * CINC + c * 8;
        const uint32_t dst = sbase + SM_B +
                             SW128((uint32_t)(r * 128 + c * 16));
        CP_ASYNC16(dst, src);
    }
    CP_COMMIT();
    CP_WAIT0();
    __syncthreads();

    // warp tile: 64 px x 32 oc.  p = wid&3 -> (h_local, px-base); wid>>2 -> oc group
    const int p       = wid & 3;
    const int h_local = p >> 1;
    const int mw      = (p & 1) * 64;      // pixel base
    const int n0      = (wid >> 2) * 32;   // oc base

    float acc[4][4][4];
#pragma unroll
    for (int i = 0; i < 4; i++)
#pragma unroll
        for (int j = 0; j < 4; j++)
#pragma unroll
            for (int e = 0; e < 4; e++) acc[i][j][e] = 0.0f;

    for (int t = 0; t < 9; t++) {
        const int b = t & 1;
        if (t < 8) {  // prefetch next tap's B into other buffer
            const int tn = t + 1;
#pragma unroll
            for (int k = 0; k < 2; k++) {
                const int idx = tid + k * 512;
                const int r = idx >> 3, c = idx & 7;
                const __half* src = g_bh + (tn * COUTC + r) * CINC + c * 8;
                const uint32_t dst = sbase + SM_B + (b ^ 1) * 16384 +
                                     SW128((uint32_t)(r * 128 + c * 16));
                CP_ASYNC16(dst, src);
            }
            CP_COMMIT();
        }

        const int kh = t / 3, kw = t - kh * 3;
        const uint32_t aT = sbase + SM_A + (h_local + kh) * 16384;
        const uint32_t bT = sbase + SM_B + b * 16384;

#pragma unroll
        for (int ks = 0; ks < 4; ks++) {
            uint32_t ah[4][4];
#pragma unroll
            for (int i = 0; i < 4; i++) {
                // row can exceed 127 for kw>0; spills into adjacent smem and
                // feeds only discarded outputs (w>=126). All bits are finite fp16.
                const int row = mw + i * 16 + (lane & 15) + kw;
                const uint32_t off =
                    SW128((uint32_t)(row * 128 + (ks * 2 + (lane >> 4)) * 16));
                ldsm_x4(aT + off, ah[i]);
            }
#pragma unroll
            for (int jj = 0; jj < 2; jj++) {
                const int quad = lane >> 3;
                const int brow = n0 + jj * 16 + (quad >> 1) * 8 + (lane & 7);
                const uint32_t boff =
                    SW128((uint32_t)(brow * 128 + (ks * 2 + (quad & 1)) * 16));
                uint32_t bf[4];
                ldsm_x4(bT + boff, bf);
#pragma unroll
                for (int i = 0; i < 4; i++) {
                    mma_fp16(acc[i][jj * 2],     ah[i], bf[0], bf[1]);
                    mma_fp16(acc[i][jj * 2 + 1], ah[i], bf[2], bf[3]);
                }
            }
        }

        if (t < 8) CP_WAIT0();
        __syncthreads();
    }

    // --- epilogue: bias + mish + BN ---
    const float* s_bias  = (const float*)(smem + SM_PAR);
    const float* s_scale = (const float*)(smem + SM_PAR + 512);
    const float* s_shift = (const float*)(smem + SM_PAR + 1024);
    const int h_out = h0 + h_local;     // <= 125, always valid

#pragma unroll
    for (int i = 0; i < 4; i++)
#pragma unroll
        for (int j = 0; j < 4; j++)
#pragma unroll
            for (int e = 0; e < 4; e++) {
                const int w  = mw + i * 16 + (lane >> 2) + ((e & 2) ? 8 : 0);
                const int oc = n0 + j * 8 + (lane & 3) * 2 + (e & 1);
                if (w < WOUTC) {
                    const float z = acc[i][j][e] + s_bias[oc];
                    // mish: z*tanh(softplus(z)) = z*v/(v+2), v = e^z*(e^z+2)
                    float u;
                    asm("ex2.approx.f32 %0, %1;" : "=f"(u) : "f"(z * 1.44269504f));
                    const float v = u * (u + 2.0f);
                    float m = z * __fdividef(v, v + 2.0f);
                    if (z > 30.0f) m = z;
                    out[(((size_t)n * COUTC + oc) * HOUTC + h_out) * WOUTC + w] =
                        fmaf(m, s_scale[oc], s_shift[oc]);
                }
            }
}

// ---------------- launch ----------------
extern "C" void kernel_launch(void* const* d_in, const int* in_sizes, int n_in,
                              void* d_out, int out_size)
{
    const float* x     = (const float*)d_in[0];
    const float* wgt   = (const float*)d_in[1];
    const float* bias  = (const float*)d_in[2];
    const float* gamma = (const float*)d_in[3];
    const float* beta  = (const float*)d_in[4];
    const float* rmean = (const float*)d_in[5];
    const float* rvar  = (const float*)d_in[6];
    float* out = (float*)d_out;

    cudaFuncSetAttribute(conv_hmma_kernel,
                         cudaFuncAttributeMaxDynamicSharedMemorySize, SMEM_TOTAL);

    wprep_kernel<<<(9 * COUTC * CINC + 255) / 256, 256>>>(wgt);
    xprep_kernel<<<dim3(HIN, NBATCH), 256>>>(x);
    conv_hmma_kernel<<<dim3(HOUTC / 2, NBATCH), 512, SMEM_TOTAL>>>(bias, gamma, beta,
                                                                   rmean, rvar, out);
}

// round 7
// speedup vs baseline: 10.0713x; 1.2165x over previous
#include <cuda_runtime.h>
#include <cuda_fp16.h>
#include <cstdint>

// Fused conv3x3-VALID + bias + mish + BN(inference), implicit GEMM on
// mma.sync m16n8k16 fp16 (x and weights fp16; rel_err ~3e-4 < 1e-3).
// Per CTA: ONE (n,h) output row, 256 threads / 8 warps, 2 CTAs per SM.
// Warp tile 64 px x 32 oc. M=128 px, N=128 oc, K=9 taps x 64 ic.

#define HIN   128
#define WIN   128
#define CINC  64
#define COUTC 128
#define HOUTC 126
#define WOUTC 126
#define NBATCH 32

__device__ __align__(16) __half g_xh[NBATCH * HIN * WIN * CINC];  // NHWC fp16
__device__ __align__(16) __half g_bh[9 * COUTC * CINC];           // [tap][oc][ic]

__device__ __forceinline__ uint32_t smem_u32(const void* p) {
    uint32_t a;
    asm("{ .reg .u64 t; cvta.to.shared.u64 t, %1; cvt.u32.u64 %0, t; }" : "=r"(a) : "l"(p));
    return a;
}
#define SW128(o) ((o) ^ (((o) >> 3) & 0x70))

#define CP_ASYNC16(dst, src) \
    asm volatile("cp.async.cg.shared.global [%0], [%1], 16;" :: "r"(dst), "l"(src) : "memory")
#define CP_COMMIT() asm volatile("cp.async.commit_group;" ::: "memory")
#define CP_WAIT0()  asm volatile("cp.async.wait_group 0;" ::: "memory")

__device__ __forceinline__ void ldsm_x4(uint32_t addr, uint32_t* r) {
    asm volatile("ldmatrix.sync.aligned.m8n8.x4.shared.b16 {%0,%1,%2,%3}, [%4];"
        : "=r"(r[0]), "=r"(r[1]), "=r"(r[2]), "=r"(r[3]) : "r"(addr));
}
__device__ __forceinline__ void mma_fp16(float* d, const uint32_t* a,
                                         uint32_t b0, uint32_t b1) {
    asm volatile("mma.sync.aligned.m16n8k16.row.col.f32.f16.f16.f32 "
        "{%0,%1,%2,%3}, {%4,%5,%6,%7}, {%8,%9}, {%0,%1,%2,%3};"
        : "+f"(d[0]), "+f"(d[1]), "+f"(d[2]), "+f"(d[3])
        : "r"(a[0]), "r"(a[1]), "r"(a[2]), "r"(a[3]), "r"(b0), "r"(b1));
}

// ---------------- prepass: weights OIHW fp32 -> [tap][oc][ic] fp16 --------
__global__ void wprep_kernel(const float* __restrict__ wgt) {
    int i = blockIdx.x * 256 + threadIdx.x;
    if (i >= 9 * COUTC * CINC) return;
    int oc = i / (9 * CINC);
    int j  = i - oc * (9 * CINC);
    int t  = j >> 6;
    int ic = j & 63;
    g_bh[(t * COUTC + oc) * CINC + ic] = __float2half(wgt[oc * 576 + ic * 9 + t]);
}

// ---------------- prepass: x NCHW fp32 -> NHWC fp16 ----------------
__global__ void xprep_kernel(const float* __restrict__ x) {
    __shared__ float s[CINC][129];
    const int h = blockIdx.x, n = blockIdx.y, tid = threadIdx.x;
    for (int i = tid; i < CINC * WIN; i += 256) {
        int ic = i >> 7, w = i & 127;
        s[ic][w] = x[(((n * CINC) + ic) * HIN + h) * WIN + w];
    }
    __syncthreads();
    const int outbase = ((n * HIN + h) * WIN) * CINC;
    for (int j = tid; j < WIN * 8; j += 256) {
        int w = j >> 3, icg = j & 7;
        __align__(16) __half h8[8];
#pragma unroll
        for (int u = 0; u < 8; u++) h8[u] = __float2half(s[icg * 8 + u][w]);
        *(uint4*)(g_xh + outbase + w * CINC + icg * 8) = *(uint4*)h8;
    }
}

// ---------------- main kernel ----------------
// smem: params(2048) | A: 3 x 16KB (input rows h..h+2) | B: 2 x 16KB dbl buf
#define SM_PAR 0
#define SM_A   2048
#define SM_B   (SM_A + 3 * 16384)
#define SMEM_TOTAL (SM_B + 2 * 16384)   // 82 KB -> 2 CTAs/SM

__global__ __launch_bounds__(256, 2)
void conv_hmma_kernel(const float* __restrict__ bias,
                      const float* __restrict__ gamma,
                      const float* __restrict__ beta,
                      const float* __restrict__ rmean,
                      const float* __restrict__ rvar,
                      float* __restrict__ out)
{
    extern __shared__ char smem[];
    const uint32_t sbase = smem_u32(smem);
    const int tid = threadIdx.x, lane = tid & 31, wid = tid >> 5;
    const int h = blockIdx.x, n = blockIdx.y;

    if (tid < COUTC) {
        const float sc = gamma[tid] * rsqrtf(rvar[tid] + 1e-5f);
        ((float*)(smem + SM_PAR))[tid]        = bias[tid];
        ((float*)(smem + SM_PAR + 512))[tid]  = sc;
        ((float*)(smem + SM_PAR + 1024))[tid] = beta[tid] - rmean[tid] * sc;
    }

    // --- stage A: 3 input rows (h..h+2), SW128, cp.async ---
#pragma unroll
    for (int k = 0; k < 12; k++) {
        const int idx  = tid + k * 256;       // 0..3071
        const int tile = idx >> 10;           // input row 0..2
        const int wit  = idx & 1023;
        const int r = wit >> 3, c = wit & 7;  // pixel w, 16B chunk
        const __half* src = g_xh + (((n * HIN + (h + tile)) * WIN) + r) * CINC + c * 8;
        const uint32_t dst = sbase + SM_A + tile * 16384 +
                             SW128((uint32_t)(r * 128 + c * 16));
        CP_ASYNC16(dst, src);
    }
    // --- stage B tap 0 ---
#pragma unroll
    for (int k = 0; k < 4; k++) {
        const int idx = tid + k * 256;        // 0..1023
        const int r = idx >> 3, c = idx & 7;  // oc, chunk
        const __half* src = g_bh + r * CINC + c * 8;
        const uint32_t dst = sbase + SM_B +
                             SW128((uint32_t)(r * 128 + c * 16));
        CP_ASYNC16(dst, src);
    }
    CP_COMMIT();
    CP_WAIT0();
    __syncthreads();

    // warp tile: 64 px x 32 oc
    const int mw = (wid & 1) * 64;      // pixel base
    const int n0 = (wid >> 1) * 32;     // oc base

    float acc[4][4][4];
#pragma unroll
    for (int i = 0; i < 4; i++)
#pragma unroll
        for (int j = 0; j < 4; j++)
#pragma unroll
            for (int e = 0; e < 4; e++) acc[i][j][e] = 0.0f;

    for (int t = 0; t < 9; t++) {
        const int b = t & 1;
        if (t < 8) {  // prefetch next tap's B into other buffer
            const int tn = t + 1;
#pragma unroll
            for (int k = 0; k < 4; k++) {
                const int idx = tid + k * 256;
                const int r = idx >> 3, c = idx & 7;
                const __half* src = g_bh + (tn * COUTC + r) * CINC + c * 8;
                const uint32_t dst = sbase + SM_B + (b ^ 1) * 16384 +
                                     SW128((uint32_t)(r * 128 + c * 16));
                CP_ASYNC16(dst, src);
            }
            CP_COMMIT();
        }

        const int kh = t / 3, kw = t - kh * 3;
        const uint32_t aT = sbase + SM_A + kh * 16384;
        const uint32_t bT = sbase + SM_B + b * 16384;

#pragma unroll
        for (int ks = 0; ks < 4; ks++) {
            uint32_t ah[4][4];
#pragma unroll
            for (int i = 0; i < 4; i++) {
                // row can exceed 127 for kw>0: reads spill into adjacent smem
                // and feed only discarded outputs (w>=126). Bits are finite fp16.
                const int row = mw + i * 16 + (lane & 15) + kw;
                const uint32_t off =
                    SW128((uint32_t)(row * 128 + (ks * 2 + (lane >> 4)) * 16));
                ldsm_x4(aT + off, ah[i]);
            }
#pragma unroll
            for (int jj = 0; jj < 2; jj++) {
                const int quad = lane >> 3;
                const int brow = n0 + jj * 16 + (quad >> 1) * 8 + (lane & 7);
                const uint32_t boff =
                    SW128((uint32_t)(brow * 128 + (ks * 2 + (quad & 1)) * 16));
                uint32_t bf[4];
                ldsm_x4(bT + boff, bf);
#pragma unroll
                for (int i = 0; i < 4; i++) {
                    mma_fp16(acc[i][jj * 2],     ah[i], bf[0], bf[1]);
                    mma_fp16(acc[i][jj * 2 + 1], ah[i], bf[2], bf[3]);
                }
            }
        }

        if (t < 8) CP_WAIT0();
        __syncthreads();
    }

    // --- epilogue: bias + mish + BN ---
    const float* s_bias  = (const float*)(smem + SM_PAR);
    const float* s_scale = (const float*)(smem + SM_PAR + 512);
    const float* s_shift = (const float*)(smem + SM_PAR + 1024);

#pragma unroll
    for (int i = 0; i < 4; i++)
#pragma unroll
        for (int j = 0; j < 4; j++)
#pragma unroll
            for (int e = 0; e < 4; e++) {
                const int w  = mw + i * 16 + (lane >> 2) + ((e & 2) ? 8 : 0);
                const int oc = n0 + j * 8 + (lane & 3) * 2 + (e & 1);
                if (w < WOUTC) {
                    const float z = acc[i][j][e] + s_bias[oc];
                    // mish: z*tanh(softplus(z)) = z*v/(v+2), v = e^z*(e^z+2)
                    float u;
                    asm("ex2.approx.f32 %0, %1;" : "=f"(u) : "f"(z * 1.44269504f));
                    const float v = u * (u + 2.0f);
                    float m = z * __fdividef(v, v + 2.0f);
                    if (z > 30.0f) m = z;
                    out[(((size_t)n * COUTC + oc) * HOUTC + h) * WOUTC + w] =
                        fmaf(m, s_scale[oc], s_shift[oc]);
                }
            }
}

// ---------------- launch ----------------
extern "C" void kernel_launch(void* const* d_in, const int* in_sizes, int n_in,
                              void* d_out, int out_size)
{
    const float* x     = (const float*)d_in[0];
    const float* wgt   = (const float*)d_in[1];
    const float* bias  = (const float*)d_in[2];
    const float* gamma = (const float*)d_in[3];
    const float* beta  = (const float*)d_in[4];
    const float* rmean = (const float*)d_in[5];
    const float* rvar  = (const float*)d_in[6];
    float* out = (float*)d_out;

    cudaFuncSetAttribute(conv_hmma_kernel,
                         cudaFuncAttributeMaxDynamicSharedMemorySize, SMEM_TOTAL);

    wprep_kernel<<<(9 * COUTC * CINC + 255) / 256, 256>>>(wgt);
    xprep_kernel<<<dim3(HIN, NBATCH), 256>>>(x);
    conv_hmma_kernel<<<dim3(HOUTC, NBATCH), 256, SMEM_TOTAL>>>(bias, gamma, beta,
                                                               rmean, rvar, out);
}